// round 7
// baseline (speedup 1.0000x reference)
#include <cuda_runtime.h>
#include <cuda_fp16.h>
#include <cstdint>

// Problem constants (fixed by the reference).
#define D_IN_   2048
#define D_SAE_  32768
#define N_      8192
#define K_      64

// Gather tiling (R3-proven): CD dims per chunk (fp16 footprint 32MB,
// L2-resident), RN rows per CTA.
#define CD      512
#define RN      16

// Persistent transpose: 4 blocks/SM x 148 SMs.
#define TB      592
#define TILES   (1024 * 32)     // 1024 s-tiles x 32 d-tiles (32s x 64d each)
#define TILES_PER_CHUNK 8192    // 8 d-tiles x 1024 s-tiles per 512-dim chunk

// Scratch (device globals — no allocation allowed in kernel_launch).
__device__ __half g_Wth[(size_t)D_SAE_ * D_IN_];  // transposed W fp16 (D_SAE, D_IN)
__device__ float  g_vals[N_ * K_];                // deduped values
__device__ int    g_chunk_done[4];                // transposed tiles per d-chunk
__device__ int    g_dedupe_done;                  // finished dedupe blocks

// ---------------------------------------------------------------------------
// Kernel 0: reset the progress flags (graph replays reuse the globals).
// ---------------------------------------------------------------------------
__global__ void zero_flags_kernel() {
    if (threadIdx.x < 4) g_chunk_done[threadIdx.x] = 0;
    if (threadIdx.x == 4) g_dedupe_done = 0;
    __threadfence();
}

// ---------------------------------------------------------------------------
// Kernel 1: PERSISTENT transpose+convert+dedupe producer.
//   - signals PDL immediately so the gather kernel can co-schedule
//   - dedupe first (gather needs g_vals early), then tiles in chunk-major
//     stripe order so chunk 0 completes at ~25% of the kernel
//   - per-tile: 32s x 64d, warp-coalesced 128B reads, __half2 128B writes,
//     tile[32][65] conflict-free (measured-good R3 shape)
// ---------------------------------------------------------------------------
__global__ __launch_bounds__(256)
void transpose_dedupe_kernel(const float* __restrict__ W,
                             const int*   __restrict__ idx,
                             const float* __restrict__ vals) {
    // Let the dependent gather kernel launch right away.
    asm volatile("griddepcontrol.launch_dependents;" ::: "memory");

    __shared__ float tile[32][65];
    __shared__ int   sidx[4][K_];

    int t  = threadIdx.x;
    int tx = t & 31;
    int ty = t >> 5;          // 0..7
    int b  = blockIdx.x;

    // ---- dedupe: reference scatter is .set() — LAST duplicate wins, so
    // zero every value whose index reappears later in the row. 4 rows/group.
    #pragma unroll 1
    for (int g = b; g < N_ / 4; g += TB) {
        int lr  = t >> 6;
        int k   = t & 63;
        int row = g * 4 + lr;
        int sv  = idx[row * K_ + k];
        sidx[lr][k] = sv;
        __syncthreads();
        bool keep = true;
        #pragma unroll 1
        for (int k2 = k + 1; k2 < K_; ++k2)
            if (sidx[lr][k2] == sv) keep = false;
        g_vals[row * K_ + k] = keep ? vals[row * K_ + k] : 0.0f;
        __syncthreads();
    }
    if (t == 0) { __threadfence(); atomicAdd(&g_dedupe_done, 1); }

    // ---- transpose tiles, chunk-major stripe: all blocks sweep chunk 0's
    // 8192 tiles first, then chunk 1, ...
    #pragma unroll 1
    for (int tt = b; tt < TILES; tt += TB) {
        int xt = tt & 1023;           // s tile index
        int yt = tt >> 10;            // d tile index (64 dims)
        int s0 = xt * 32;
        int d0 = yt * 64;

        #pragma unroll
        for (int j = 0; j < 8; ++j)
            tile[tx][ty * 8 + j] =
                W[(size_t)(d0 + ty * 8 + j) * D_SAE_ + s0 + tx];  // 128B/warp
        __syncthreads();

        #pragma unroll
        for (int j = 0; j < 4; ++j) {
            int sl = ty + 8 * j;
            int dl = tx * 2;
            __half2 h = __floats2half2_rn(tile[sl][dl], tile[sl][dl + 1]);
            *reinterpret_cast<__half2*>(
                &g_Wth[(size_t)(s0 + sl) * D_IN_ + d0 + dl]) = h;  // 128B/warp
        }
        __syncthreads();
        if (t == 0) { __threadfence(); atomicAdd(&g_chunk_done[yt >> 3], 1); }
    }
}

// ---------------------------------------------------------------------------
// Kernel 2: gather-FMA consumer — byte-identical R3 body (the measured
// optimum: LDG.128, 8 dims/thread, fp32 FFMA, bias in regs, no reg clamp),
// preceded by a spin on this chunk's readiness flag.
//   grid = (512 row-tiles, 4 chunks), chunk = SLOW axis (L2 residency).
// ---------------------------------------------------------------------------
__global__ __launch_bounds__(256)
void gather_kernel(const int* __restrict__ idx,
                   const float* __restrict__ b_dec,
                   float* __restrict__ out) {
    __shared__ int   soff[RN][K_];
    __shared__ float sval[RN][K_];

    int r0  = blockIdx.x * RN;
    int d0  = blockIdx.y * CD;
    int tid = threadIdx.x;

    // Wait until this d-chunk is transposed and values are deduped.
    if (tid == 0) {
        volatile int* cd = &g_chunk_done[blockIdx.y];
        volatile int* dd = &g_dedupe_done;
        while (*cd != TILES_PER_CHUNK) __nanosleep(256);
        while (*dd != TB)              __nanosleep(64);
        __threadfence();
    }
    __syncthreads();

    #pragma unroll
    for (int i = tid; i < RN * K_; i += 256) {
        soff[0][i] = idx[r0 * K_ + i] * D_IN_;
        sval[0][i] = g_vals[r0 * K_ + i];
    }
    __syncthreads();

    int td = tid & 63;            // dim-thread
    int tr = tid >> 6;            // row group 0..3
    int d  = d0 + td * 8;         // 8 contiguous dims (16B fp16) per thread

    float bb[8];
    {
        float4 b0 = *reinterpret_cast<const float4*>(b_dec + d);
        float4 b1 = *reinterpret_cast<const float4*>(b_dec + d + 4);
        bb[0] = b0.x; bb[1] = b0.y; bb[2] = b0.z; bb[3] = b0.w;
        bb[4] = b1.x; bb[5] = b1.y; bb[6] = b1.z; bb[7] = b1.w;
    }

    const __half* Wt = g_Wth;

    #pragma unroll 1
    for (int i = 0; i < 4; ++i) {
        int r = tr * 4 + i;
        float acc[8];
        #pragma unroll
        for (int j = 0; j < 8; ++j) acc[j] = bb[j];

        #pragma unroll 8
        for (int k = 0; k < K_; ++k) {
            int   off = soff[r][k] + d;
            float v   = sval[r][k];
            uint4 w   = *reinterpret_cast<const uint4*>(Wt + off);
            __half2 h0 = *reinterpret_cast<__half2*>(&w.x);
            __half2 h1 = *reinterpret_cast<__half2*>(&w.y);
            __half2 h2 = *reinterpret_cast<__half2*>(&w.z);
            __half2 h3 = *reinterpret_cast<__half2*>(&w.w);
            float2 f0 = __half22float2(h0);
            float2 f1 = __half22float2(h1);
            float2 f2 = __half22float2(h2);
            float2 f3 = __half22float2(h3);
            acc[0] = fmaf(v, f0.x, acc[0]);
            acc[1] = fmaf(v, f0.y, acc[1]);
            acc[2] = fmaf(v, f1.x, acc[2]);
            acc[3] = fmaf(v, f1.y, acc[3]);
            acc[4] = fmaf(v, f2.x, acc[4]);
            acc[5] = fmaf(v, f2.y, acc[5]);
            acc[6] = fmaf(v, f3.x, acc[6]);
            acc[7] = fmaf(v, f3.y, acc[7]);
        }

        float* orow = out + (size_t)(r0 + r) * D_IN_ + d;
        // Streaming stores: don't let the 64MB output evict the W chunk in L2.
        __stcs(reinterpret_cast<float4*>(orow),
               make_float4(acc[0], acc[1], acc[2], acc[3]));
        __stcs(reinterpret_cast<float4*>(orow + 4),
               make_float4(acc[4], acc[5], acc[6], acc[7]));
    }
}

// ---------------------------------------------------------------------------
// Launch. Inputs (metadata order): indices(int32 N*K), values(f32 N*K),
// W_dec(f32 D_IN*D_SAE), b_dec(f32 D_IN). Output: f32 N*D_IN.
// Graph-capturable: 3 kernel launches (gather uses PDL so it co-schedules
// with the persistent transpose); zero allocation, zero sync.
// ---------------------------------------------------------------------------
extern "C" void kernel_launch(void* const* d_in, const int* in_sizes, int n_in,
                              void* d_out, int out_size) {
    const int*   indices = (const int*)  d_in[0];
    const float* values  = (const float*)d_in[1];
    const float* W       = (const float*)d_in[2];
    const float* b       = (const float*)d_in[3];
    float*       out     = (float*)d_out;

    zero_flags_kernel<<<1, 32>>>();

    transpose_dedupe_kernel<<<TB, 256>>>(W, indices, values);

    cudaLaunchConfig_t cfg = {};
    cfg.gridDim  = dim3(N_ / RN, D_IN_ / CD);   // 512 x 4, chunk = slow axis
    cfg.blockDim = dim3(256);
    cfg.stream   = 0;
    cudaLaunchAttribute at[1];
    at[0].id = cudaLaunchAttributeProgrammaticStreamSerialization;
    at[0].val.programmaticStreamSerializationAllowed = 1;
    cfg.attrs    = at;
    cfg.numAttrs = 1;
    cudaLaunchKernelEx(&cfg, gather_kernel, indices, b, out);
}

// round 9
// speedup vs baseline: 1.0085x; 1.0085x over previous
#include <cuda_runtime.h>
#include <cuda_fp16.h>
#include <cstdint>

// Problem constants (fixed by the reference).
#define D_IN_   2048
#define D_SAE_  32768
#define N_      8192
#define K_      64

// Gather tiling (R3-proven): CD dims per chunk (fp16 footprint 32MB,
// L2-resident), RN rows per CTA. 512 row-tiles x 4 chunks = 2048 tiles.
#define CD      512
#define RN      16
#define RTILES  (N_ / RN)                 // 512
#define GTILES  (RTILES * (D_IN_ / CD))   // 2048
#define GB      740                       // persistent gather CTAs (5/SM x 148)

// Scratch (device globals — no allocation allowed in kernel_launch).
__device__ __half g_Wth[(size_t)D_SAE_ * D_IN_];  // transposed W fp16 (D_SAE, D_IN)
__device__ float  g_vals[N_ * K_];                // deduped values

// ---------------------------------------------------------------------------
// Kernel 1 (fused, EXACT R3 shape — proven correct & fast): transpose+convert
// W_dec (D_IN, D_SAE) fp32 -> g_Wth (D_SAE, D_IN) fp16, AND dedupe values
// (folded into the first 2048 blocks).
// Tile 32 s x 64 d: warp-coalesced 128B scalar reads, __half2-packed 128B
// writes, tile[32][65] conflict-free on both phases, all accesses 4B-aligned.
// ---------------------------------------------------------------------------
__global__ __launch_bounds__(256)
void transpose_dedupe_kernel(const float* __restrict__ W,
                             const int*   __restrict__ idx,
                             const float* __restrict__ vals) {
    __shared__ float tile[32][65];

    int tx = threadIdx.x & 31;
    int ty = threadIdx.x >> 5;   // 0..7

    int s = blockIdx.x * 32 + tx;
    #pragma unroll
    for (int j = 0; j < 8; ++j) {
        int d = blockIdx.y * 64 + ty * 8 + j;
        tile[tx][ty * 8 + j] = W[(size_t)d * D_SAE_ + s];   // 128B/warp read
    }
    __syncthreads();

    #pragma unroll
    for (int j = 0; j < 4; ++j) {
        int s_local = ty + 8 * j;
        int d_local = tx * 2;
        __half2 h = __floats2half2_rn(tile[s_local][d_local],
                                      tile[s_local][d_local + 1]);
        *reinterpret_cast<__half2*>(
            &g_Wth[(size_t)(blockIdx.x * 32 + s_local) * D_IN_
                   + blockIdx.y * 64 + d_local]) = h;       // 128B/warp write
    }

    // Dedupe (first 2048 blocks; 4 rows each). Reference scatter is .set():
    // LAST duplicate wins -> zero values whose index reappears later.
    int bid = blockIdx.y * gridDim.x + blockIdx.x;
    if (bid < N_ / 4) {
        __shared__ int sidx[4][K_];
        int t   = threadIdx.x;
        int lr  = t >> 6;
        int k   = t & 63;
        int row = bid * 4 + lr;
        int sv  = idx[row * K_ + k];
        sidx[lr][k] = sv;
        __syncthreads();
        bool keep = true;
        #pragma unroll 1
        for (int k2 = k + 1; k2 < K_; ++k2)
            if (sidx[lr][k2] == sv) keep = false;
        g_vals[row * K_ + k] = keep ? vals[row * K_ + k] : 0.0f;
    }
}

// ---------------------------------------------------------------------------
// Kernel 2: PERSISTENT gather-FMA. Inner body byte-identical to the
// measured-best R3 kernel (LDG.128, 8 dims/thread, fp32 FFMA, bias in regs,
// no reg clamp). 740 CTAs loop chunk-major over 2048 logical tiles -> no
// partial tail wave; concurrent CTAs span <=2 adjacent chunks (<=64MB, L2).
// ---------------------------------------------------------------------------
__global__ __launch_bounds__(256)
void gather_kernel(const int* __restrict__ idx,
                   const float* __restrict__ b_dec,
                   float* __restrict__ out) {
    __shared__ int   soff[RN][K_];
    __shared__ float sval[RN][K_];

    int tid = threadIdx.x;
    int td  = tid & 63;           // dim-thread
    int tr  = tid >> 6;           // row group 0..3

    const __half* Wt = g_Wth;

    #pragma unroll 1
    for (int tt = blockIdx.x; tt < GTILES; tt += GB) {
        int r0 = (tt & (RTILES - 1)) * RN;    // row tile (fast)
        int d0 = (tt >> 9) * CD;              // chunk    (slow)

        __syncthreads();   // previous iteration's smem reads complete
        #pragma unroll
        for (int i = tid; i < RN * K_; i += 256) {
            soff[0][i] = idx[r0 * K_ + i] * D_IN_;
            sval[0][i] = g_vals[r0 * K_ + i];
        }
        __syncthreads();

        int d = d0 + td * 8;      // 8 contiguous dims (16B fp16) per thread

        float bb[8];
        {
            float4 b0 = *reinterpret_cast<const float4*>(b_dec + d);
            float4 b1 = *reinterpret_cast<const float4*>(b_dec + d + 4);
            bb[0] = b0.x; bb[1] = b0.y; bb[2] = b0.z; bb[3] = b0.w;
            bb[4] = b1.x; bb[5] = b1.y; bb[6] = b1.z; bb[7] = b1.w;
        }

        #pragma unroll 1
        for (int i = 0; i < 4; ++i) {
            int r = tr * 4 + i;
            float acc[8];
            #pragma unroll
            for (int j = 0; j < 8; ++j) acc[j] = bb[j];

            #pragma unroll 8
            for (int k = 0; k < K_; ++k) {
                int   off = soff[r][k] + d;
                float v   = sval[r][k];
                uint4 w   = *reinterpret_cast<const uint4*>(Wt + off);
                __half2 h0 = *reinterpret_cast<__half2*>(&w.x);
                __half2 h1 = *reinterpret_cast<__half2*>(&w.y);
                __half2 h2 = *reinterpret_cast<__half2*>(&w.z);
                __half2 h3 = *reinterpret_cast<__half2*>(&w.w);
                float2 f0 = __half22float2(h0);
                float2 f1 = __half22float2(h1);
                float2 f2 = __half22float2(h2);
                float2 f3 = __half22float2(h3);
                acc[0] = fmaf(v, f0.x, acc[0]);
                acc[1] = fmaf(v, f0.y, acc[1]);
                acc[2] = fmaf(v, f1.x, acc[2]);
                acc[3] = fmaf(v, f1.y, acc[3]);
                acc[4] = fmaf(v, f2.x, acc[4]);
                acc[5] = fmaf(v, f2.y, acc[5]);
                acc[6] = fmaf(v, f3.x, acc[6]);
                acc[7] = fmaf(v, f3.y, acc[7]);
            }

            float* orow = out + (size_t)(r0 + r) * D_IN_ + d;
            // Streaming stores: keep the 64MB output from evicting W in L2.
            __stcs(reinterpret_cast<float4*>(orow),
                   make_float4(acc[0], acc[1], acc[2], acc[3]));
            __stcs(reinterpret_cast<float4*>(orow + 4),
                   make_float4(acc[4], acc[5], acc[6], acc[7]));
        }
    }
}

// ---------------------------------------------------------------------------
// Launch. Inputs (metadata order): indices(int32 N*K), values(f32 N*K),
// W_dec(f32 D_IN*D_SAE), b_dec(f32 D_IN). Output: f32 N*D_IN.
// Graph-capturable: 2 plain kernel launches, zero allocation, zero sync.
// ---------------------------------------------------------------------------
extern "C" void kernel_launch(void* const* d_in, const int* in_sizes, int n_in,
                              void* d_out, int out_size) {
    const int*   indices = (const int*)  d_in[0];
    const float* values  = (const float*)d_in[1];
    const float* W       = (const float*)d_in[2];
    const float* b       = (const float*)d_in[3];
    float*       out     = (float*)d_out;

    dim3 tg(D_SAE_ / 32, D_IN_ / 64);
    transpose_dedupe_kernel<<<tg, 256>>>(W, indices, values);

    gather_kernel<<<GB, 256>>>(indices, b, out);
}

// round 10
// speedup vs baseline: 1.0831x; 1.0739x over previous
#include <cuda_runtime.h>
#include <cuda_fp16.h>
#include <cstdint>

// Problem constants (fixed by the reference).
#define D_IN_   2048
#define D_SAE_  32768
#define N_      8192
#define K_      64

// Gather tiling (R3-proven): CD dims per chunk (fp16 footprint 32MB,
// L2-resident), RN rows per CTA.
#define CD      512
#define RN      16

// Scratch (device globals — no allocation allowed in kernel_launch).
__device__ __half g_Wth[(size_t)D_SAE_ * D_IN_];  // transposed W fp16 (D_SAE, D_IN)
__device__ float  g_vals[N_ * K_];                // deduped values

// ---------------------------------------------------------------------------
// Kernel 1 (fused): transpose+convert W_dec (D_IN, D_SAE) fp32 -> g_Wth
// (D_SAE, D_IN) fp16, AND dedupe values (folded into the first 2048 blocks).
//
// Tile 32 s x 64 d, tile[32][68] (8.7KB smem -> occupancy preserved):
//   read : LDG.128 x2/thread; STS.32 scatter, banks 4(s4+j)+dl distinct
//          within quarter-warp -> conflict-free
//   write: LDS.128 x2/thread (row stride 272B = 16B-aligned; verified),
//          STG.128 of 8 packed halves, (d0+dc)*2B = 16B-aligned
// ---------------------------------------------------------------------------
__global__ __launch_bounds__(256)
void transpose_dedupe_kernel(const float* __restrict__ W,
                             const int*   __restrict__ idx,
                             const float* __restrict__ vals) {
    __shared__ float tile[32][68];   // [s_local][d_local], pad 4 (16B-aligned rows)

    int t  = threadIdx.x;            // 0..255
    int s0 = blockIdx.x * 32;
    int d0 = blockIdx.y * 64;

    // ---- read phase: 64 d-rows x 8 float4 = 512 tasks, 2 iters ----
    #pragma unroll
    for (int i = 0; i < 2; ++i) {
        int e  = i * 256 + t;
        int dl = e >> 3;             // d_local 0..63
        int s4 = (e & 7) * 4;        // s_local, float4 granularity
        float4 v = *reinterpret_cast<const float4*>(
            W + (size_t)(d0 + dl) * D_SAE_ + s0 + s4);
        tile[s4 + 0][dl] = v.x;
        tile[s4 + 1][dl] = v.y;
        tile[s4 + 2][dl] = v.z;
        tile[s4 + 3][dl] = v.w;
    }
    __syncthreads();

    // ---- write phase: 32 s-rows x 8 uint4 tasks = 256, 1 per thread ----
    {
        int sl = t >> 3;             // s_local 0..31
        int dc = (t & 7) * 8;        // d_local base (8 dims)
        float4 f0 = *reinterpret_cast<const float4*>(&tile[sl][dc]);
        float4 f1 = *reinterpret_cast<const float4*>(&tile[sl][dc + 4]);
        __half2 h0 = __floats2half2_rn(f0.x, f0.y);
        __half2 h1 = __floats2half2_rn(f0.z, f0.w);
        __half2 h2 = __floats2half2_rn(f1.x, f1.y);
        __half2 h3 = __floats2half2_rn(f1.z, f1.w);
        uint4 o;
        o.x = *reinterpret_cast<uint32_t*>(&h0);
        o.y = *reinterpret_cast<uint32_t*>(&h1);
        o.z = *reinterpret_cast<uint32_t*>(&h2);
        o.w = *reinterpret_cast<uint32_t*>(&h3);
        *reinterpret_cast<uint4*>(
            &g_Wth[(size_t)(s0 + sl) * D_IN_ + d0 + dc]) = o;
    }

    // ---- dedupe (first 2048 blocks; 4 rows each). Reference scatter is
    // .set(): LAST duplicate wins -> zero values whose index reappears later.
    int bid = blockIdx.y * gridDim.x + blockIdx.x;
    if (bid < N_ / 4) {
        __shared__ int sidx[4][K_];
        int lr  = t >> 6;
        int k   = t & 63;
        int row = bid * 4 + lr;
        int sv  = idx[row * K_ + k];
        sidx[lr][k] = sv;
        __syncthreads();
        bool keep = true;
        #pragma unroll 1
        for (int k2 = k + 1; k2 < K_; ++k2)
            if (sidx[lr][k2] == sv) keep = false;
        g_vals[row * K_ + k] = keep ? vals[row * K_ + k] : 0.0f;
    }
}

// ---------------------------------------------------------------------------
// Kernel 2: gather-FMA — EXACT R3 kernel and launch shape (measured best:
// 126us, L2 70.8%). LDG.128, 8 dims/thread, fp32 FFMA, bias in regs, no reg
// clamp, 2048-CTA wave-synchronized chunk sweep (persistence regressed R9).
// ---------------------------------------------------------------------------
__global__ __launch_bounds__(256)
void gather_kernel(const int* __restrict__ idx,
                   const float* __restrict__ b_dec,
                   float* __restrict__ out) {
    __shared__ int   soff[RN][K_];
    __shared__ float sval[RN][K_];

    int r0  = blockIdx.x * RN;
    int d0  = blockIdx.y * CD;
    int tid = threadIdx.x;

    #pragma unroll
    for (int i = tid; i < RN * K_; i += 256) {
        soff[0][i] = idx[r0 * K_ + i] * D_IN_;
        sval[0][i] = g_vals[r0 * K_ + i];
    }
    __syncthreads();

    int td = tid & 63;            // dim-thread
    int tr = tid >> 6;            // row group 0..3
    int d  = d0 + td * 8;         // 8 contiguous dims (16B fp16) per thread

    float bb[8];
    {
        float4 b0 = *reinterpret_cast<const float4*>(b_dec + d);
        float4 b1 = *reinterpret_cast<const float4*>(b_dec + d + 4);
        bb[0] = b0.x; bb[1] = b0.y; bb[2] = b0.z; bb[3] = b0.w;
        bb[4] = b1.x; bb[5] = b1.y; bb[6] = b1.z; bb[7] = b1.w;
    }

    const __half* Wt = g_Wth;

    #pragma unroll 1
    for (int i = 0; i < 4; ++i) {
        int r = tr * 4 + i;
        float acc[8];
        #pragma unroll
        for (int j = 0; j < 8; ++j) acc[j] = bb[j];

        #pragma unroll 8
        for (int k = 0; k < K_; ++k) {
            int   off = soff[r][k] + d;
            float v   = sval[r][k];
            uint4 w   = *reinterpret_cast<const uint4*>(Wt + off);
            __half2 h0 = *reinterpret_cast<__half2*>(&w.x);
            __half2 h1 = *reinterpret_cast<__half2*>(&w.y);
            __half2 h2 = *reinterpret_cast<__half2*>(&w.z);
            __half2 h3 = *reinterpret_cast<__half2*>(&w.w);
            float2 f0 = __half22float2(h0);
            float2 f1 = __half22float2(h1);
            float2 f2 = __half22float2(h2);
            float2 f3 = __half22float2(h3);
            acc[0] = fmaf(v, f0.x, acc[0]);
            acc[1] = fmaf(v, f0.y, acc[1]);
            acc[2] = fmaf(v, f1.x, acc[2]);
            acc[3] = fmaf(v, f1.y, acc[3]);
            acc[4] = fmaf(v, f2.x, acc[4]);
            acc[5] = fmaf(v, f2.y, acc[5]);
            acc[6] = fmaf(v, f3.x, acc[6]);
            acc[7] = fmaf(v, f3.y, acc[7]);
        }

        float* orow = out + (size_t)(r0 + r) * D_IN_ + d;
        // Streaming stores: don't let the 64MB output evict the W chunk in L2.
        __stcs(reinterpret_cast<float4*>(orow),
               make_float4(acc[0], acc[1], acc[2], acc[3]));
        __stcs(reinterpret_cast<float4*>(orow + 4),
               make_float4(acc[4], acc[5], acc[6], acc[7]));
    }
}

// ---------------------------------------------------------------------------
// Launch. Inputs (metadata order): indices(int32 N*K), values(f32 N*K),
// W_dec(f32 D_IN*D_SAE), b_dec(f32 D_IN). Output: f32 N*D_IN.
// Graph-capturable: 2 plain kernel launches, zero allocation, zero sync.
// ---------------------------------------------------------------------------
extern "C" void kernel_launch(void* const* d_in, const int* in_sizes, int n_in,
                              void* d_out, int out_size) {
    const int*   indices = (const int*)  d_in[0];
    const float* values  = (const float*)d_in[1];
    const float* W       = (const float*)d_in[2];
    const float* b       = (const float*)d_in[3];
    float*       out     = (float*)d_out;

    dim3 tg(D_SAE_ / 32, D_IN_ / 64);
    transpose_dedupe_kernel<<<tg, 256>>>(W, indices, values);

    dim3 gg(N_ / RN, D_IN_ / CD);   // x = row tiles (fast), y = d-chunks (slow)
    gather_kernel<<<gg, 256>>>(indices, b, out);
}

// round 11
// speedup vs baseline: 1.1241x; 1.0379x over previous
#include <cuda_runtime.h>
#include <cuda_fp16.h>
#include <cstdint>

// Problem constants (fixed by the reference).
#define D_IN_   2048
#define D_SAE_  32768
#define N_      8192
#define K_      64

// Gather tiling (R3-proven): CD dims per chunk (fp16 footprint 32MB,
// L2-resident), RN rows per CTA.
#define CD      512
#define RN      16

// Scratch (device globals — no allocation allowed in kernel_launch).
__device__ __half g_Wth[(size_t)D_SAE_ * D_IN_];  // transposed W fp16 (D_SAE, D_IN)
__device__ float  g_vals[N_ * K_];                // deduped values

// ---------------------------------------------------------------------------
// Kernel 1 (fused): transpose+convert W_dec (D_IN, D_SAE) fp32 -> g_Wth
// (D_SAE, D_IN) fp16, AND dedupe values (folded into the first 2048 blocks).
//
// Tile 32 s x 64 d, tile[32][65] (8.3KB smem):
//   read : LDG.128 x2/thread (s0+s4 16B-aligned); STS.32 scatter with banks
//          (s4 + j + dl) mod 32 = 4(t&7) + (t>>3) + c -> all 32 DISTINCT
//          within a warp (pad-65 arithmetic verified; pad-68 in R10 was the
//          4-way-conflict bug).
//   write: EXACT R3 phase — scalar LDS + __half2 STG.32, 128B/warp, measured
//          good.
// ---------------------------------------------------------------------------
__global__ __launch_bounds__(256)
void transpose_dedupe_kernel(const float* __restrict__ W,
                             const int*   __restrict__ idx,
                             const float* __restrict__ vals) {
    __shared__ float tile[32][65];   // [s_local][d_local]

    int t  = threadIdx.x;            // 0..255
    int tx = t & 31;
    int ty = t >> 5;                 // 0..7
    int s0 = blockIdx.x * 32;
    int d0 = blockIdx.y * 64;

    // ---- read phase: 64 d-rows x 8 float4 = 512 tasks, 2 iters ----
    #pragma unroll
    for (int i = 0; i < 2; ++i) {
        int e  = i * 256 + t;
        int dl = e >> 3;             // d_local 0..63
        int s4 = (e & 7) * 4;        // s_local, float4 granularity
        float4 v = *reinterpret_cast<const float4*>(
            W + (size_t)(d0 + dl) * D_SAE_ + s0 + s4);
        tile[s4 + 0][dl] = v.x;
        tile[s4 + 1][dl] = v.y;
        tile[s4 + 2][dl] = v.z;
        tile[s4 + 3][dl] = v.w;
    }
    __syncthreads();

    // ---- write phase (exact R3): 4 half2 per thread, 128B/warp STG ----
    #pragma unroll
    for (int j = 0; j < 4; ++j) {
        int s_local = ty + 8 * j;
        int d_local = tx * 2;
        __half2 h = __floats2half2_rn(tile[s_local][d_local],
                                      tile[s_local][d_local + 1]);
        *reinterpret_cast<__half2*>(
            &g_Wth[(size_t)(s0 + s_local) * D_IN_ + d0 + d_local]) = h;
    }

    // ---- dedupe (first 2048 blocks; 4 rows each). Reference scatter is
    // .set(): LAST duplicate wins -> zero values whose index reappears later.
    int bid = blockIdx.y * gridDim.x + blockIdx.x;
    if (bid < N_ / 4) {
        __shared__ int sidx[4][K_];
        int lr  = t >> 6;
        int k   = t & 63;
        int row = bid * 4 + lr;
        int sv  = idx[row * K_ + k];
        sidx[lr][k] = sv;
        __syncthreads();
        bool keep = true;
        #pragma unroll 1
        for (int k2 = k + 1; k2 < K_; ++k2)
            if (sidx[lr][k2] == sv) keep = false;
        g_vals[row * K_ + k] = keep ? vals[row * K_ + k] : 0.0f;
    }
}

// ---------------------------------------------------------------------------
// Kernel 2: gather-FMA — EXACT R3 kernel and launch shape (measured best:
// ~125us, L2 72%, at the LTS throughput ceiling). LDG.128, 8 dims/thread,
// fp32 FFMA, bias in regs, no reg clamp, 2048-CTA wave-synchronized chunk
// sweep. DO NOT MODIFY (R4/R5/R6/R9 excursions all regressed).
// ---------------------------------------------------------------------------
__global__ __launch_bounds__(256)
void gather_kernel(const int* __restrict__ idx,
                   const float* __restrict__ b_dec,
                   float* __restrict__ out) {
    __shared__ int   soff[RN][K_];
    __shared__ float sval[RN][K_];

    int r0  = blockIdx.x * RN;
    int d0  = blockIdx.y * CD;
    int tid = threadIdx.x;

    #pragma unroll
    for (int i = tid; i < RN * K_; i += 256) {
        soff[0][i] = idx[r0 * K_ + i] * D_IN_;
        sval[0][i] = g_vals[r0 * K_ + i];
    }
    __syncthreads();

    int td = tid & 63;            // dim-thread
    int tr = tid >> 6;            // row group 0..3
    int d  = d0 + td * 8;         // 8 contiguous dims (16B fp16) per thread

    float bb[8];
    {
        float4 b0 = *reinterpret_cast<const float4*>(b_dec + d);
        float4 b1 = *reinterpret_cast<const float4*>(b_dec + d + 4);
        bb[0] = b0.x; bb[1] = b0.y; bb[2] = b0.z; bb[3] = b0.w;
        bb[4] = b1.x; bb[5] = b1.y; bb[6] = b1.z; bb[7] = b1.w;
    }

    const __half* Wt = g_Wth;

    #pragma unroll 1
    for (int i = 0; i < 4; ++i) {
        int r = tr * 4 + i;
        float acc[8];
        #pragma unroll
        for (int j = 0; j < 8; ++j) acc[j] = bb[j];

        #pragma unroll 8
        for (int k = 0; k < K_; ++k) {
            int   off = soff[r][k] + d;
            float v   = sval[r][k];
            uint4 w   = *reinterpret_cast<const uint4*>(Wt + off);
            __half2 h0 = *reinterpret_cast<__half2*>(&w.x);
            __half2 h1 = *reinterpret_cast<__half2*>(&w.y);
            __half2 h2 = *reinterpret_cast<__half2*>(&w.z);
            __half2 h3 = *reinterpret_cast<__half2*>(&w.w);
            float2 f0 = __half22float2(h0);
            float2 f1 = __half22float2(h1);
            float2 f2 = __half22float2(h2);
            float2 f3 = __half22float2(h3);
            acc[0] = fmaf(v, f0.x, acc[0]);
            acc[1] = fmaf(v, f0.y, acc[1]);
            acc[2] = fmaf(v, f1.x, acc[2]);
            acc[3] = fmaf(v, f1.y, acc[3]);
            acc[4] = fmaf(v, f2.x, acc[4]);
            acc[5] = fmaf(v, f2.y, acc[5]);
            acc[6] = fmaf(v, f3.x, acc[6]);
            acc[7] = fmaf(v, f3.y, acc[7]);
        }

        float* orow = out + (size_t)(r0 + r) * D_IN_ + d;
        // Streaming stores: don't let the 64MB output evict the W chunk in L2.
        __stcs(reinterpret_cast<float4*>(orow),
               make_float4(acc[0], acc[1], acc[2], acc[3]));
        __stcs(reinterpret_cast<float4*>(orow + 4),
               make_float4(acc[4], acc[5], acc[6], acc[7]));
    }
}

// ---------------------------------------------------------------------------
// Launch. Inputs (metadata order): indices(int32 N*K), values(f32 N*K),
// W_dec(f32 D_IN*D_SAE), b_dec(f32 D_IN). Output: f32 N*D_IN.
// Graph-capturable: 2 plain kernel launches, zero allocation, zero sync.
// ---------------------------------------------------------------------------
extern "C" void kernel_launch(void* const* d_in, const int* in_sizes, int n_in,
                              void* d_out, int out_size) {
    const int*   indices = (const int*)  d_in[0];
    const float* values  = (const float*)d_in[1];
    const float* W       = (const float*)d_in[2];
    const float* b       = (const float*)d_in[3];
    float*       out     = (float*)d_out;

    dim3 tg(D_SAE_ / 32, D_IN_ / 64);
    transpose_dedupe_kernel<<<tg, 256>>>(W, indices, values);

    dim3 gg(N_ / RN, D_IN_ / CD);   // x = row tiles (fast), y = d-chunks (slow)
    gather_kernel<<<gg, 256>>>(indices, b, out);
}